// round 17
// baseline (speedup 1.0000x reference)
#include <cuda_runtime.h>
#include <cuda_bf16.h>
#include <cstdint>

// Problem constants
#define Bb 2
#define Ss 2048
#define Ee 1024
#define Hh 16
#define Dd 64
#define BHh (Bb*Hh)

typedef unsigned int u32;
typedef unsigned short u16;

// ---------------- device scratch (no allocations allowed) ----------------
__device__ uint4 g_pxh[256*64*32], g_pxl[256*64*32];   // hidden A-pack
__device__ uint4 g_pah[256*64*32], g_pal[256*64*32];   // attn-out A-pack (proj input)
__device__ uint4 g_pwah[384*64*16], g_pwal[384*64*16]; // W_attn^T B-pack
__device__ uint4 g_pwph[128*64*16], g_pwpl[128*64*16]; // W_proj^T B-pack
// Flash packs (per bh): Q A-pack (m=s,k=d), K B-pack (n=key,k=d), V B-pack (n=d,k=key)
__device__ u32 g_qph[32*128*4*32*4], g_qpl[32*128*4*32*4];
__device__ u32 g_kph[32*32*8*4*32*2], g_kpl[32*32*8*4*32*2];
__device__ u32 g_vph[32*32*8*4*32*2], g_vpl[32*32*8*4*32*2];

__device__ __forceinline__ u32 bfpack(float a, float b) {
    __nv_bfloat16 ha = __float2bfloat16(a), hb = __float2bfloat16(b);
    return (u32)__bfloat16_as_ushort(ha) | ((u32)__bfloat16_as_ushort(hb) << 16);
}
__device__ __forceinline__ float bflow(float x) {
    return x - __bfloat162float(__float2bfloat16(x));
}
__device__ __forceinline__ u16 bfbits(float x) {
    return __bfloat16_as_ushort(__float2bfloat16(x));
}
__device__ __forceinline__ u32 smem_u32(const void* p) {
    u32 a; asm("{ .reg .u64 t; cvta.to.shared.u64 t, %1; cvt.u32.u64 %0, t; }" : "=r"(a) : "l"(p));
    return a;
}
// cp.async helpers (sm_80+, OK under compute_103)
__device__ __forceinline__ void cp16(u32 s, const void* g) {
    asm volatile("cp.async.cg.shared.global [%0], [%1], 16;" :: "r"(s), "l"(g));
}
__device__ __forceinline__ void cp_commit() { asm volatile("cp.async.commit_group;"); }
__device__ __forceinline__ void cp_wait1()  { asm volatile("cp.async.wait_group 1;"); }
__device__ __forceinline__ void cp_wait0()  { asm volatile("cp.async.wait_group 0;"); }

// ---------------- mma.sync wrapper (bf16 -> fp32) ----------------
__device__ __forceinline__ void mma_bf16(float4& c, uint4 a, uint2 b) {
    asm volatile("mma.sync.aligned.m16n8k16.row.col.f32.bf16.bf16.f32 "
        "{%0,%1,%2,%3}, {%4,%5,%6,%7}, {%8,%9}, {%0,%1,%2,%3};"
        : "+f"(c.x), "+f"(c.y), "+f"(c.z), "+f"(c.w)
        : "r"(a.x), "r"(a.y), "r"(a.z), "r"(a.w), "r"(b.x), "r"(b.y));
}

// ---------------- pre-pass: split fp32 activations -> packed bf16 hi/lo ----
__global__ void __launch_bounds__(256)
split_pack_A(const float* __restrict__ X, uint4* __restrict__ H4, uint4* __restrict__ L4)
{
    u32* H = (u32*)H4; u32* L = (u32*)L4;
    int gid = blockIdx.x * 256 + threadIdx.x;   // one per 8 elems
    int m = gid >> 7;
    int kg = (gid & 127) * 8;
    const float* p = X + (size_t)m * 1024 + kg;
    float4 v0 = *(const float4*)p, v1 = *(const float4*)(p + 4);
    float xs[8] = {v0.x, v0.y, v0.z, v0.w, v1.x, v1.y, v1.z, v1.w};
    int mt = m >> 4, ks = kg >> 4, mhi = (m >> 3) & 1, k8 = (kg >> 3) & 1;
    int base = (((mt*64 + ks)*32) + (m & 7)*4) * 4 + (k8*2 + mhi);
    #pragma unroll
    for (int t = 0; t < 4; t++) {
        float e0 = xs[2*t], e1 = xs[2*t+1];
        H[base + t*4] = bfpack(e0, e1);
        L[base + t*4] = bfpack(bflow(e0), bflow(e1));
    }
}

// ---------------- pre-pass: transpose+split weights -> packed bf16 hi/lo ---
__global__ void __launch_bounds__(256)
tsplit_pack_B(const float* __restrict__ W, uint4* __restrict__ H4, uint4* __restrict__ L4, int N)
{
    u32* H = (u32*)H4; u32* L = (u32*)L4;
    __shared__ float t[32][33];
    const int k0 = blockIdx.y * 32, n0 = blockIdx.x * 32;
    const int r = threadIdx.x >> 3, c4 = (threadIdx.x & 7) * 4;
    float4 v = *(const float4*)&W[(size_t)(k0 + r) * N + n0 + c4];
    t[r][c4+0] = v.x; t[r][c4+1] = v.y; t[r][c4+2] = v.z; t[r][c4+3] = v.w;
    __syncthreads();
    const int n = n0 + r, kk = k0 + c4;
    float e[4];
    #pragma unroll
    for (int i = 0; i < 4; i++) e[i] = t[c4 + i][r];
    int nt = n >> 3, ks = kk >> 4, k8 = (kk >> 3) & 1;
    int tp = (kk & 7) >> 1;
    int idx = (((nt*64 + ks)*32) + (n & 7)*4 + tp) * 2 + k8;
    H[idx]     = bfpack(e[0], e[1]);
    H[idx + 2] = bfpack(e[2], e[3]);
    L[idx]     = bfpack(bflow(e[0]), bflow(e[1]));
    L[idx + 2] = bfpack(bflow(e[2]), bflow(e[3]));
}

// ---------------- tensor-core (mma.sync) bf16-split GEMM ----------------
// cp.async 3-stage ring, ONE __syncthreads per chunk, 2 CTAs/SM.
// Stage s (32KB) at uint4 offset s*2048: Ah[0,512) Al[512,1024) Bh[1024,1536) Bl[1536,2048).
template<int MODE>
__global__ void __launch_bounds__(256, 2)
gemm_mma(const uint4* __restrict__ Ah, const uint4* __restrict__ Al,
         const uint4* __restrict__ Bh, const uint4* __restrict__ Bl,
         const float* __restrict__ bias, float* __restrict__ Cout,
         u32* __restrict__ QH, u32* __restrict__ QL,
         u32* __restrict__ KH, u32* __restrict__ KL,
         u16* __restrict__ VHs, u16* __restrict__ VLs,
         int Ndim)
{
    extern __shared__ uint4 dynsm[];
    const u32 sbase = smem_u32(dynsm);

    const int tid = threadIdx.x;
    const int lane = tid & 31, wid = tid >> 5;
    const int wm = wid & 1, wn = wid >> 1;
    const int m0 = blockIdx.y * 128, n0 = blockIdx.x * 128;
    const int m0t = m0 >> 4, n0t = n0 >> 3;

    const int ia0 = tid, ia1 = tid + 256;
    #define A_G(idx) ((((size_t)(m0t + ((idx) >> 6)) * 64 + (((idx) >> 5) & 1)) * 32) + ((idx) & 31))
    #define A_S(idx) (((((idx) >> 5) & 1) * 8 + ((idx) >> 6)) * 32 + ((idx) & 31))
    #define B_G(idx) ((((size_t)(n0t + ((idx) >> 5)) * 64 + (((idx) >> 4) & 1)) * 16) + ((idx) & 15))
    #define B_S(idx) (((((idx) >> 4) & 1) * 16 + ((idx) >> 5)) * 16 + ((idx) & 15))
    const uint4 *pAh0 = Ah + A_G(ia0), *pAh1 = Ah + A_G(ia1);
    const uint4 *pAl0 = Al + A_G(ia0), *pAl1 = Al + A_G(ia1);
    const uint4 *pBh0 = Bh + B_G(ia0), *pBh1 = Bh + B_G(ia1);
    const uint4 *pBl0 = Bl + B_G(ia0), *pBl1 = Bl + B_G(ia1);
    const u32 sa0 = (u32)A_S(ia0)*16, sa1 = (u32)A_S(ia1)*16;
    const u32 sb0 = (u32)B_S(ia0)*16, sb1 = (u32)B_S(ia1)*16;

    #define ISSUE(CK) do { \
        u32 bb = sbase + ((CK) % 3) * 32768; \
        size_t ao = (size_t)(CK)*64, bo = (size_t)(CK)*32; \
        cp16(bb + sa0, pAh0 + ao);          cp16(bb + sa1, pAh1 + ao); \
        cp16(bb + 8192 + sa0, pAl0 + ao);   cp16(bb + 8192 + sa1, pAl1 + ao); \
        cp16(bb + 16384 + sb0, pBh0 + bo);  cp16(bb + 16384 + sb1, pBh1 + bo); \
        cp16(bb + 24576 + sb0, pBl0 + bo);  cp16(bb + 24576 + sb1, pBl1 + bo); \
        cp_commit(); \
    } while (0)

    float4 acc[4][4];
    #pragma unroll
    for (int i = 0; i < 4; i++)
        #pragma unroll
        for (int j = 0; j < 4; j++) acc[i][j] = make_float4(0.f, 0.f, 0.f, 0.f);

    ISSUE(0); ISSUE(1);
    for (int ck = 0; ck < 32; ck++) {
        if (ck < 31) cp_wait1(); else cp_wait0();
        __syncthreads();                         // single barrier per chunk
        if (ck + 2 < 32) ISSUE(ck + 2);          // buf (ck+2)%3: all warps done with it

        const uint4* st4  = dynsm + (ck % 3) * 2048;
        const uint4* stAh = st4;
        const uint4* stAl = st4 + 512;
        const uint2* stBh = (const uint2*)(st4 + 1024);
        const uint2* stBl = (const uint2*)(st4 + 1536);

        #pragma unroll
        for (int ks = 0; ks < 2; ks++) {
            uint2 bh[4], bl[4];
            #pragma unroll
            for (int j = 0; j < 4; j++) {
                int bi = (ks*16 + wn*4 + j)*32 + lane;
                bh[j] = stBh[bi];
                bl[j] = stBl[bi];
            }
            #pragma unroll
            for (int i = 0; i < 4; i++) {
                int aidx = (ks*8 + wm*4 + i)*32 + lane;
                uint4 ah = stAh[aidx];
                uint4 al = stAl[aidx];
                #pragma unroll
                for (int j = 0; j < 4; j++) {
                    mma_bf16(acc[i][j], ah, bh[j]);
                    mma_bf16(acc[i][j], ah, bl[j]);
                    mma_bf16(acc[i][j], al, bh[j]);
                }
            }
        }
    }

    const int g = lane >> 2, t2 = (lane & 3) * 2;
    #pragma unroll
    for (int i = 0; i < 4; i++) {
        int r1 = m0 + wm*64 + i*16 + g;
        #pragma unroll
        for (int j = 0; j < 4; j++) {
            int cg = n0 + wn*32 + j*8 + t2;
            float2 bs = *(const float2*)(bias + cg);
            #pragma unroll
            for (int rr = 0; rr < 2; rr++) {
                int r = r1 + rr*8;
                float ex = (rr ? acc[i][j].z : acc[i][j].x) + bs.x;
                float ey = (rr ? acc[i][j].w : acc[i][j].y) + bs.y;
                if (MODE == 1) {
                    *(float2*)&Cout[(size_t)r * Ndim + cg] = make_float2(ex, ey);
                } else {
                    int b = r >> 11, s = r & 2047;
                    int part = cg >> 10, e = cg & 1023;
                    int h = e >> 6, d = e & 63, bh = b*Hh + h;
                    if (part == 0) {
                        ex *= 0.0625f; ey *= 0.0625f;   // 1/(sqrt(64)*layer_idx)
                        int mt = s >> 4, ks = d >> 4;
                        int li = (s & 7)*4 + ((d & 7) >> 1);
                        int rg = ((d >> 3) & 1)*2 + ((s >> 3) & 1);
                        int qi = (((bh*128 + mt)*4 + ks)*32 + li)*4 + rg;
                        QH[qi] = bfpack(ex, ey);
                        QL[qi] = bfpack(bflow(ex), bflow(ey));
                    } else if (part == 1) {
                        int kt = s >> 6, nt = (s & 63) >> 3;
                        int ks = d >> 4, k8 = (d >> 3) & 1;
                        int li = (s & 7)*4 + ((d & 7) >> 1);
                        int ki = ((((bh*32 + kt)*8 + nt)*4 + ks)*32 + li)*2 + k8;
                        KH[ki] = bfpack(ex, ey);
                        KL[ki] = bfpack(bflow(ex), bflow(ey));
                    } else {
                        int kt = s >> 6, kk = s & 63;
                        int ks = kk >> 4, k8 = (kk >> 3) & 1, hf = kk & 1;
                        #pragma unroll
                        for (int dd = 0; dd < 2; dd++) {
                            float v = dd ? ey : ex;
                            int d2 = d + dd;
                            int nt = d2 >> 3;
                            int li = (d2 & 7)*4 + ((kk & 7) >> 1);
                            int ui = (((((bh*32 + kt)*8 + nt)*4 + ks)*32 + li)*2 + k8)*2 + hf;
                            VHs[ui] = bfbits(v);
                            VLs[ui] = bfbits(bflow(v));
                        }
                    }
                }
            }
        }
    }
}

// ---------------------------------------------------------------------------
// Tensor-core flash attention, 2 CTAs/SM.
// Dyn smem: Q pack [0,2048) uint4 (hi 0-1023, lo 1024-2047), then K/V stage s
// (32KB) at uint4 offset 2048 + s*2048: Kh[0,512) Kl[512,1024) Vh Vl.
// Q loaded once via cp.async (folded into first pipeline group).
// ---------------------------------------------------------------------------
__global__ void __launch_bounds__(256, 2)
flash_mma(const u32* __restrict__ QH, const u32* __restrict__ QL,
          const uint2* __restrict__ KH, const uint2* __restrict__ KL,
          const uint2* __restrict__ VH, const uint2* __restrict__ VL,
          u32* __restrict__ PAH, u32* __restrict__ PAL)
{
    extern __shared__ uint4 dynsm[];
    const u32 sbase = smem_u32(dynsm);

    const int tid = threadIdx.x, lane = tid & 31, w = tid >> 5;
    const int qt = (int)gridDim.x - 1 - (int)blockIdx.x;  // big tiles first
    const int bh = blockIdx.y;
    const int q0 = qt * 128;
    const int g = lane >> 2, t = lane & 3;

    // ---- Q tile -> smem via cp.async (1024 uint4 hi + 1024 lo) ----
    {
        const uint4* gqh = (const uint4*)QH + (size_t)(bh*128 + (q0 >> 4)) * 128;
        const uint4* gql = (const uint4*)QL + (size_t)(bh*128 + (q0 >> 4)) * 128;
        #pragma unroll
        for (int i = 0; i < 4; i++) {
            int idx = tid + i*256;
            cp16(sbase + idx*16, gqh + idx);
            cp16(sbase + 16384 + idx*16, gql + idx);
        }
    }

    float4 O[8];
    #pragma unroll
    for (int j = 0; j < 8; j++) O[j] = make_float4(0.f, 0.f, 0.f, 0.f);
    float m0_ = -1e30f, m1_ = -1e30f, l0 = 0.f, l1 = 0.f;
    const int rlo = q0 + w*16 + g, rhi = rlo + 8;
    const int wlast = q0 + w*16 + 15;
    const int wfirst = q0 + w*16;

    const int ntiles = 2*qt + 2;

    #define FISSUE(KT) do { \
        u32 bb = sbase + 32768 + ((KT) & 1) * 32768; \
        size_t toff = (size_t)(bh*32 + (KT)) * 512; \
        const uint4* gkh = (const uint4*)KH + toff; \
        const uint4* gkl = (const uint4*)KL + toff; \
        const uint4* gvh = (const uint4*)VH + toff; \
        const uint4* gvl = (const uint4*)VL + toff; \
        cp16(bb + tid*16, gkh + tid);                 cp16(bb + (tid+256)*16, gkh + tid + 256); \
        cp16(bb + 8192 + tid*16, gkl + tid);          cp16(bb + 8192 + (tid+256)*16, gkl + tid + 256); \
        cp16(bb + 16384 + tid*16, gvh + tid);         cp16(bb + 16384 + (tid+256)*16, gvh + tid + 256); \
        cp16(bb + 24576 + tid*16, gvl + tid);         cp16(bb + 24576 + (tid+256)*16, gvl + tid + 256); \
        cp_commit(); \
    } while (0)

    FISSUE(0);   // Q copies + first K/V tile commit as one group
    for (int kt = 0; kt < ntiles; kt++) {
        if (kt + 1 < ntiles) { FISSUE(kt + 1); cp_wait1(); }
        else                 { cp_wait0(); }
        __syncthreads();

        const uint4* st4 = dynsm + 2048 + (kt & 1) * 2048;
        const uint2* sKh = (const uint2*)st4;
        const uint2* sKl = (const uint2*)(st4 + 512);
        const uint2* sVh = (const uint2*)(st4 + 1024);
        const uint2* sVl = (const uint2*)(st4 + 1536);

        const int k0 = kt * 64;
        if (k0 <= wlast) {
            // ---- S = Q K^T (scaled; 3-term split) ----
            float4 S[8];
            #pragma unroll
            for (int j = 0; j < 8; j++) S[j] = make_float4(0.f, 0.f, 0.f, 0.f);
            #pragma unroll
            for (int ks = 0; ks < 4; ks++) {
                uint4 qh = dynsm[(w*4 + ks)*32 + lane];
                uint4 ql = dynsm[1024 + (w*4 + ks)*32 + lane];
                #pragma unroll
                for (int j = 0; j < 8; j++) {
                    uint2 kb = sKh[(j*4 + ks)*32 + lane];
                    uint2 kl = sKl[(j*4 + ks)*32 + lane];
                    mma_bf16(S[j], qh, kb);
                    mma_bf16(S[j], qh, kl);
                    mma_bf16(S[j], ql, kb);
                }
            }
            // ---- causal mask ----
            if (k0 + 63 > wfirst) {
                #pragma unroll
                for (int j = 0; j < 8; j++) {
                    int c0 = k0 + j*8 + 2*t, c1 = c0 + 1;
                    if (c0 > rlo) S[j].x = -10000.f;
                    if (c1 > rlo) S[j].y = -10000.f;
                    if (c0 > rhi) S[j].z = -10000.f;
                    if (c1 > rhi) S[j].w = -10000.f;
                }
            }
            // ---- online softmax (rows g / g+8; quad reduce) ----
            float mx0 = -1e30f, mx1 = -1e30f;
            #pragma unroll
            for (int j = 0; j < 8; j++) {
                mx0 = fmaxf(mx0, fmaxf(S[j].x, S[j].y));
                mx1 = fmaxf(mx1, fmaxf(S[j].z, S[j].w));
            }
            mx0 = fmaxf(mx0, __shfl_xor_sync(0xffffffffu, mx0, 1));
            mx0 = fmaxf(mx0, __shfl_xor_sync(0xffffffffu, mx0, 2));
            mx1 = fmaxf(mx1, __shfl_xor_sync(0xffffffffu, mx1, 1));
            mx1 = fmaxf(mx1, __shfl_xor_sync(0xffffffffu, mx1, 2));
            float mn0 = fmaxf(m0_, mx0), mn1 = fmaxf(m1_, mx1);
            float c0 = __expf(m0_ - mn0), c1 = __expf(m1_ - mn1);
            m0_ = mn0; m1_ = mn1;
            float s0 = 0.f, s1 = 0.f;
            #pragma unroll
            for (int j = 0; j < 8; j++) {
                S[j].x = __expf(S[j].x - mn0);
                S[j].y = __expf(S[j].y - mn0);
                S[j].z = __expf(S[j].z - mn1);
                S[j].w = __expf(S[j].w - mn1);
                s0 += S[j].x + S[j].y;
                s1 += S[j].z + S[j].w;
            }
            s0 += __shfl_xor_sync(0xffffffffu, s0, 1);
            s0 += __shfl_xor_sync(0xffffffffu, s0, 2);
            s1 += __shfl_xor_sync(0xffffffffu, s1, 1);
            s1 += __shfl_xor_sync(0xffffffffu, s1, 2);
            l0 = l0*c0 + s0;
            l1 = l1*c1 + s1;
            #pragma unroll
            for (int j = 0; j < 8; j++) {
                O[j].x *= c0; O[j].y *= c0;
                O[j].z *= c1; O[j].w *= c1;
            }
            // ---- P (C-frag) -> A-frag register-local; O += P V ----
            #pragma unroll
            for (int kc = 0; kc < 4; kc++) {
                float4 A = S[2*kc], B = S[2*kc + 1];
                uint4 ph, pl;
                ph.x = bfpack(A.x, A.y); ph.y = bfpack(A.z, A.w);
                ph.z = bfpack(B.x, B.y); ph.w = bfpack(B.z, B.w);
                pl.x = bfpack(bflow(A.x), bflow(A.y));
                pl.y = bfpack(bflow(A.z), bflow(A.w));
                pl.z = bfpack(bflow(B.x), bflow(B.y));
                pl.w = bfpack(bflow(B.z), bflow(B.w));
                #pragma unroll
                for (int j = 0; j < 8; j++) {
                    uint2 vh = sVh[(j*4 + kc)*32 + lane];
                    uint2 vl = sVl[(j*4 + kc)*32 + lane];
                    mma_bf16(O[j], ph, vh);
                    mma_bf16(O[j], ph, vl);
                    mma_bf16(O[j], pl, vh);
                }
            }
        }
        __syncthreads();
    }

    // ---- epilogue: normalize + write proj A-pack (hi/lo) ----
    const float i0 = 1.f / l0, i1 = 1.f / l1;
    const int b = bh >> 4, h = bh & 15;
    const int mtp = (b*2048 + q0 + w*16) >> 4;
    #pragma unroll
    for (int j = 0; j < 8; j++) {
        int ksp = h*4 + (j >> 1);
        int base = ((mtp*64 + ksp)*32 + g*4 + t)*4 + (j & 1)*2;
        float x = O[j].x * i0, y = O[j].y * i0;
        float z = O[j].z * i1, wv = O[j].w * i1;
        PAH[base + 0] = bfpack(x, y);
        PAL[base + 0] = bfpack(bflow(x), bflow(y));
        PAH[base + 1] = bfpack(z, wv);
        PAL[base + 1] = bfpack(bflow(z), bflow(wv));
    }
}

// ---------------------------------------------------------------------------
extern "C" void kernel_launch(void* const* d_in, const int* in_sizes, int n_in,
                              void* d_out, int out_size)
{
    const float* hs     = (const float*)d_in[0];
    const float* w_attn = (const float*)d_in[1];
    const float* b_attn = (const float*)d_in[2];
    const float* w_proj = (const float*)d_in[3];
    const float* b_proj = (const float*)d_in[4];
    float* out = (float*)d_out;

    uint4 *pxh, *pxl, *pah, *pal, *pwah, *pwal, *pwph, *pwpl;
    u32 *qph, *qpl, *kph, *kpl, *vph, *vpl;
    cudaGetSymbolAddress((void**)&pxh,  g_pxh);  cudaGetSymbolAddress((void**)&pxl,  g_pxl);
    cudaGetSymbolAddress((void**)&pah,  g_pah);  cudaGetSymbolAddress((void**)&pal,  g_pal);
    cudaGetSymbolAddress((void**)&pwah, g_pwah); cudaGetSymbolAddress((void**)&pwal, g_pwal);
    cudaGetSymbolAddress((void**)&pwph, g_pwph); cudaGetSymbolAddress((void**)&pwpl, g_pwpl);
    cudaGetSymbolAddress((void**)&qph,  g_qph);  cudaGetSymbolAddress((void**)&qpl,  g_qpl);
    cudaGetSymbolAddress((void**)&kph,  g_kph);  cudaGetSymbolAddress((void**)&kpl,  g_kpl);
    cudaGetSymbolAddress((void**)&vph,  g_vph);  cudaGetSymbolAddress((void**)&vpl,  g_vpl);

    const int gemm_smem  = 98304;   // 3 stages x 32KB
    const int flash_smem = 98304;   // Q 32KB + 2 stages x 32KB
    cudaFuncSetAttribute(gemm_mma<0>, cudaFuncAttributeMaxDynamicSharedMemorySize, gemm_smem);
    cudaFuncSetAttribute(gemm_mma<1>, cudaFuncAttributeMaxDynamicSharedMemorySize, gemm_smem);
    cudaFuncSetAttribute(flash_mma,   cudaFuncAttributeMaxDynamicSharedMemorySize, flash_smem);

    // 0) pack inputs (split + fragment layout)
    split_pack_A<<<(Bb*Ss*Ee)/(256*8), 256>>>(hs, pxh, pxl);
    tsplit_pack_B<<<dim3(3*Ee/32, Ee/32), 256>>>(w_attn, pwah, pwal, 3*Ee);
    tsplit_pack_B<<<dim3(Ee/32,   Ee/32), 256>>>(w_proj, pwph, pwpl, Ee);

    // 1) QKV GEMM (tensor cores); epilogue packs Q(1/16)/K/V flash fragments
    gemm_mma<0><<<dim3(3*Ee/128, (Bb*Ss)/128), 256, gemm_smem>>>(
        pxh, pxl, pwah, pwal, b_attn, nullptr,
        qph, qpl, kph, kpl, (u16*)vph, (u16*)vpl, 3*Ee);

    // 2) causal flash attention (tensor cores); writes proj A-pack
    flash_mma<<<dim3(Ss/128, BHh), 256, flash_smem>>>(
        qph, qpl, (const uint2*)kph, (const uint2*)kpl,
        (const uint2*)vph, (const uint2*)vpl, (u32*)pah, (u32*)pal);

    // 3) projection GEMM (tensor cores) -> d_out
    gemm_mma<1><<<dim3(Ee/128, (Bb*Ss)/128), 256, gemm_smem>>>(
        pah, pal, pwph, pwpl, b_proj, out,
        nullptr, nullptr, nullptr, nullptr, nullptr, nullptr, Ee);
}